// round 12
// baseline (speedup 1.0000x reference)
#include <cuda_runtime.h>
#include <cuda_bf16.h>

#define M 512
#define NBLK 1024          // 512 row-lines + 512 col-lines
#define MARGIN 0.2f
#define NT 256             // threads per CTA
#define NB 256             // buckets == threads
#define CSLOT 4            // direct-mapped neg slots per bucket

__device__ float2 g_partials[NBLK];
__device__ int    g_count = 0;     // last-block ticket; reset by the finalizing block

__global__ __launch_bounds__(NT, 8)
void side_kernel(const float* __restrict__ scores,
                 const int* __restrict__ labels,
                 float* __restrict__ out) {
    __shared__ int   cnt[NB];          // neg count per bucket
    __shared__ float fsum[NB];         // neg value sum per bucket
    __shared__ float NVS[NB * CSLOT];  // direct-mapped neg slots
    __shared__ float sufC[NB];         // count of negs in buckets > t (as float)
    __shared__ float sufS[NB];         // sum   of negs in buckets > t
    __shared__ int   OVK[M];           // overflow bucket ids (worst case all)
    __shared__ float OVX[M];           // overflow values
    __shared__ int   ovn;
    __shared__ int   wci[8];
    __shared__ float wcf[8];
    __shared__ float warp_sums[8];
    __shared__ bool  is_last;

    const int b    = blockIdx.x;
    const int t    = threadIdx.x;
    const int lane = t & 31;
    const int w    = t >> 5;

    // each thread owns elements t and t+256 of the line
    int idx0, idx1;
    if (b < M) { idx0 = b * M + t;       idx1 = idx0 + NT; }
    else       { idx0 = t * M + (b - M); idx1 = idx0 + NT * M; }

    const float s0 = scores[idx0];
    const float s1 = scores[idx1];
    const bool  p0 = (labels[idx0] == 1);
    const bool  p1 = (labels[idx1] == 1);
    const float x0 = p0 ? s0 : (s0 + MARGIN);
    const float x1 = p1 ? s1 : (s1 + MARGIN);

    cnt[t]  = 0;
    fsum[t] = 0.f;
    if (t == 0) ovn = 0;
    __syncthreads();

    // monotone bucket: floor((x+8)*16), clamped to [0,255].
    // floor+clamp is monotone: k(a) > k(b) => a > b, so the cross-bucket
    // suffix part is exact; same-bucket pairs are handled by direct relu.
    const int k0 = max(0, min(NB - 1, __float2int_rd((x0 + 8.0f) * 16.0f)));
    const int k1 = max(0, min(NB - 1, __float2int_rd((x1 + 8.0f) * 16.0f)));

    // ---- histogram + direct-mapped scatter in ONE pass ----
    if (!p0) {
        int r = atomicAdd(&cnt[k0], 1);
        if (r < CSLOT) NVS[k0 * CSLOT + r] = x0;
        else { int o = atomicAdd(&ovn, 1); OVK[o] = k0; OVX[o] = x0; }
        atomicAdd(&fsum[k0], x0);
    }
    if (!p1) {
        int r = atomicAdd(&cnt[k1], 1);
        if (r < CSLOT) NVS[k1 * CSLOT + r] = x1;
        else { int o = atomicAdd(&ovn, 1); OVK[o] = k1; OVX[o] = x1; }
        atomicAdd(&fsum[k1], x1);
    }
    __syncthreads();

    // ---- block-wide inclusive scan over 256 buckets ----
    const int   c0 = cnt[t];
    const float f0 = fsum[t];
    int   c = c0;
    float f = f0;
    #pragma unroll
    for (int o = 1; o < 32; o <<= 1) {
        int   nc = __shfl_up_sync(0xffffffffu, c, o);
        float nf = __shfl_up_sync(0xffffffffu, f, o);
        if (lane >= o) { c += nc; f += nf; }
    }
    if (lane == 31) { wci[w] = c; wcf[w] = f; }
    __syncthreads();

    if (t < 32) {
        int   ci = (t < 8) ? wci[t] : 0;
        float fi = (t < 8) ? wcf[t] : 0.f;
        #pragma unroll
        for (int o = 1; o < 8; o <<= 1) {
            int   nc = __shfl_up_sync(0xffffffffu, ci, o);
            float nf = __shfl_up_sync(0xffffffffu, fi, o);
            if (lane >= o) { ci += nc; fi += nf; }
        }
        if (t < 8) { wci[t] = ci; wcf[t] = fi; }   // inclusive warp totals
    }
    __syncthreads();

    const int   incC = c + ((w > 0) ? wci[w - 1] : 0);
    const float incF = f + ((w > 0) ? wcf[w - 1] : 0.f);
    const int   nn   = wci[7];
    const float totF = wcf[7];

    sufC[t] = (float)(nn - incC);
    sufS[t] = totF - incF;
    __syncthreads();

    // ---- per-pos evaluation: exact suffix part + same-bucket relu ----
    const int nov = ovn;
    float total = 0.f;
    if (p0) {
        float a = fmaf(-sufC[k0], s0, sufS[k0]);
        const int ck = cnt[k0];
        const int lim = min(ck, CSLOT);
        #pragma unroll
        for (int j = 0; j < CSLOT; j++)            // independent LDS, issue together
            if (j < lim) a += fmaxf(NVS[k0 * CSLOT + j] - s0, 0.f);
        if (ck > CSLOT)
            for (int j = 0; j < nov; j++)
                if (OVK[j] == k0) a += fmaxf(OVX[j] - s0, 0.f);
        total += a;
    }
    if (p1) {
        float a = fmaf(-sufC[k1], s1, sufS[k1]);
        const int ck = cnt[k1];
        const int lim = min(ck, CSLOT);
        #pragma unroll
        for (int j = 0; j < CSLOT; j++)
            if (j < lim) a += fmaxf(NVS[k1 * CSLOT + j] - s1, 0.f);
        if (ck > CSLOT)
            for (int j = 0; j < nov; j++)
                if (OVK[j] == k1) a += fmaxf(OVX[j] - s1, 0.f);
        total += a;
    }

    // ---- deterministic CTA reduction ----
    #pragma unroll
    for (int o = 16; o > 0; o >>= 1)
        total += __shfl_down_sync(0xffffffffu, total, o);
    if (lane == 0) warp_sums[w] = total;
    __syncthreads();

    if (t < 32) {
        float v = (t < 8) ? warp_sums[t] : 0.f;
        #pragma unroll
        for (int o = 4; o > 0; o >>= 1)
            v += __shfl_down_sync(0xffffffffu, v, o);
        if (t == 0) {
            const int   np    = M - nn;
            const bool  valid = (np > 0) && (nn > 0);
            const float cntf  = (float)np * (float)nn;   // exact in fp32
            float2 p;
            p.x = valid ? (v / cntf) : 0.f;
            p.y = valid ? 1.f : 0.f;
            g_partials[b] = p;
            __threadfence();
            int cc2 = atomicAdd(&g_count, 1);
            is_last = (cc2 == NBLK - 1);
        }
    }
    __syncthreads();

    // ---- last block: fixed-order global reduction + finalize ----
    if (is_last) {
        float m = 0.f, vv = 0.f;
        #pragma unroll
        for (int i = t; i < NBLK; i += NT) {
            float2 p = g_partials[i];
            m  += p.x;
            vv += p.y;
        }
        #pragma unroll
        for (int o = 16; o > 0; o >>= 1) {
            m  += __shfl_down_sync(0xffffffffu, m, o);
            vv += __shfl_down_sync(0xffffffffu, vv, o);
        }
        if (lane == 0) { warp_sums[w] = m; wcf[w] = vv; }
        __syncthreads();
        if (t < 32) {
            m  = (t < 8) ? warp_sums[t] : 0.f;
            vv = (t < 8) ? wcf[t] : 0.f;
            #pragma unroll
            for (int o = 4; o > 0; o >>= 1) {
                m  += __shfl_down_sync(0xffffffffu, m, o);
                vv += __shfl_down_sync(0xffffffffu, vv, o);
            }
            if (t == 0) {
                out[0] = m / vv;
                g_count = 0;                    // reset for next graph replay
            }
        }
    }
}

extern "C" void kernel_launch(void* const* d_in, const int* in_sizes, int n_in,
                              void* d_out, int out_size) {
    const float* scores = (const float*)d_in[0];
    const int*   labels = (const int*)d_in[1];
    float* out = (float*)d_out;

    side_kernel<<<NBLK, NT>>>(scores, labels, out);
}

// round 13
// speedup vs baseline: 1.0453x; 1.0453x over previous
#include <cuda_runtime.h>
#include <cuda_bf16.h>

#define M 512
#define NBLK 1024          // 512 row-lines + 512 col-lines
#define MARGIN 0.2f
#define NT 256             // threads per CTA
#define NB 256             // buckets == threads
#define CSLOT 5            // direct-mapped neg slots per bucket
#define CSTRIDE 5          // 5 coprime to 32 -> slot addrs spread all banks

__device__ float2 g_partials[NBLK];
__device__ int    g_count = 0;     // last-block ticket; reset by the finalizing block

__global__ __launch_bounds__(NT, 8)
void side_kernel(const float* __restrict__ scores,
                 const int* __restrict__ labels,
                 float* __restrict__ out) {
    __shared__ int   cnt[NB];            // neg count per bucket
    __shared__ float fsum[NB];           // neg value sum per bucket
    __shared__ float NVS[NB * CSTRIDE];  // direct-mapped neg slots (stride 5)
    __shared__ float sufC[NB];           // count of negs in buckets > t (as float)
    __shared__ float sufS[NB];           // sum   of negs in buckets > t
    __shared__ int   OVK[M];             // overflow bucket ids (worst case all negs)
    __shared__ float OVX[M];             // overflow values
    __shared__ int   ovn;
    __shared__ int   wci[8];
    __shared__ float wcf[8];
    __shared__ float warp_sums[8];
    __shared__ bool  is_last;

    const int b    = blockIdx.x;
    const int t    = threadIdx.x;
    const int lane = t & 31;
    const int w    = t >> 5;

    // each thread owns elements t and t+256 of the line
    int idx0, idx1;
    if (b < M) { idx0 = b * M + t;       idx1 = idx0 + NT; }
    else       { idx0 = t * M + (b - M); idx1 = idx0 + NT * M; }

    const float s0 = scores[idx0];
    const float s1 = scores[idx1];
    const bool  p0 = (labels[idx0] == 1);
    const bool  p1 = (labels[idx1] == 1);
    const float x0 = p0 ? s0 : (s0 + MARGIN);
    const float x1 = p1 ? s1 : (s1 + MARGIN);

    cnt[t]  = 0;
    fsum[t] = 0.f;
    if (t == 0) ovn = 0;
    __syncthreads();

    // monotone bucket: floor((x+8)*16), clamped to [0,255].
    // floor+clamp is monotone: k(a) > k(b) => a > b, so the cross-bucket
    // suffix part is exact; same-bucket pairs are handled by direct relu.
    const int k0 = max(0, min(NB - 1, __float2int_rd((x0 + 8.0f) * 16.0f)));
    const int k1 = max(0, min(NB - 1, __float2int_rd((x1 + 8.0f) * 16.0f)));

    // ---- histogram + direct-mapped scatter in ONE pass ----
    if (!p0) {
        int r = atomicAdd(&cnt[k0], 1);
        if (r < CSLOT) NVS[k0 * CSTRIDE + r] = x0;
        else { int o = atomicAdd(&ovn, 1); OVK[o] = k0; OVX[o] = x0; }
        atomicAdd(&fsum[k0], x0);
    }
    if (!p1) {
        int r = atomicAdd(&cnt[k1], 1);
        if (r < CSLOT) NVS[k1 * CSTRIDE + r] = x1;
        else { int o = atomicAdd(&ovn, 1); OVK[o] = k1; OVX[o] = x1; }
        atomicAdd(&fsum[k1], x1);
    }
    __syncthreads();

    // ---- block-wide inclusive scan over 256 buckets ----
    const int   c0 = cnt[t];
    const float f0 = fsum[t];
    int   c = c0;
    float f = f0;
    #pragma unroll
    for (int o = 1; o < 32; o <<= 1) {
        int   nc = __shfl_up_sync(0xffffffffu, c, o);
        float nf = __shfl_up_sync(0xffffffffu, f, o);
        if (lane >= o) { c += nc; f += nf; }
    }
    if (lane == 31) { wci[w] = c; wcf[w] = f; }
    __syncthreads();

    if (t < 32) {
        int   ci = (t < 8) ? wci[t] : 0;
        float fi = (t < 8) ? wcf[t] : 0.f;
        #pragma unroll
        for (int o = 1; o < 8; o <<= 1) {
            int   nc = __shfl_up_sync(0xffffffffu, ci, o);
            float nf = __shfl_up_sync(0xffffffffu, fi, o);
            if (lane >= o) { ci += nc; fi += nf; }
        }
        if (t < 8) { wci[t] = ci; wcf[t] = fi; }   // inclusive warp totals
    }
    __syncthreads();

    const int   incC = c + ((w > 0) ? wci[w - 1] : 0);
    const float incF = f + ((w > 0) ? wcf[w - 1] : 0.f);
    const int   nn   = wci[7];
    const float totF = wcf[7];

    sufC[t] = (float)(nn - incC);
    sufS[t] = totF - incF;
    __syncthreads();

    // ---- per-pos evaluation: exact suffix part + same-bucket relu ----
    const int nov = ovn;
    float total = 0.f;
    if (p0) {
        float a = fmaf(-sufC[k0], s0, sufS[k0]);
        const int ck  = cnt[k0];
        const int lim = min(ck, CSLOT);
        for (int j = 0; j < lim; j++)               // avg ~1 iteration
            a += fmaxf(NVS[k0 * CSTRIDE + j] - s0, 0.f);
        if (ck > CSLOT)
            for (int j = 0; j < nov; j++)
                if (OVK[j] == k0) a += fmaxf(OVX[j] - s0, 0.f);
        total += a;
    }
    if (p1) {
        float a = fmaf(-sufC[k1], s1, sufS[k1]);
        const int ck  = cnt[k1];
        const int lim = min(ck, CSLOT);
        for (int j = 0; j < lim; j++)
            a += fmaxf(NVS[k1 * CSTRIDE + j] - s1, 0.f);
        if (ck > CSLOT)
            for (int j = 0; j < nov; j++)
                if (OVK[j] == k1) a += fmaxf(OVX[j] - s1, 0.f);
        total += a;
    }

    // ---- deterministic CTA reduction ----
    #pragma unroll
    for (int o = 16; o > 0; o >>= 1)
        total += __shfl_down_sync(0xffffffffu, total, o);
    if (lane == 0) warp_sums[w] = total;
    __syncthreads();

    if (t < 32) {
        float v = (t < 8) ? warp_sums[t] : 0.f;
        #pragma unroll
        for (int o = 4; o > 0; o >>= 1)
            v += __shfl_down_sync(0xffffffffu, v, o);
        if (t == 0) {
            const int   np    = M - nn;
            const bool  valid = (np > 0) && (nn > 0);
            const float cntf  = (float)np * (float)nn;   // exact in fp32
            float2 p;
            p.x = valid ? (v / cntf) : 0.f;
            p.y = valid ? 1.f : 0.f;
            g_partials[b] = p;
            __threadfence();
            int cc2 = atomicAdd(&g_count, 1);
            is_last = (cc2 == NBLK - 1);
        }
    }
    __syncthreads();

    // ---- last block: fixed-order global reduction + finalize ----
    if (is_last) {
        float m = 0.f, vv = 0.f;
        #pragma unroll
        for (int i = t; i < NBLK; i += NT) {
            float2 p = g_partials[i];
            m  += p.x;
            vv += p.y;
        }
        #pragma unroll
        for (int o = 16; o > 0; o >>= 1) {
            m  += __shfl_down_sync(0xffffffffu, m, o);
            vv += __shfl_down_sync(0xffffffffu, vv, o);
        }
        if (lane == 0) { warp_sums[w] = m; wcf[w] = vv; }
        __syncthreads();
        if (t < 32) {
            m  = (t < 8) ? warp_sums[t] : 0.f;
            vv = (t < 8) ? wcf[t] : 0.f;
            #pragma unroll
            for (int o = 4; o > 0; o >>= 1) {
                m  += __shfl_down_sync(0xffffffffu, m, o);
                vv += __shfl_down_sync(0xffffffffu, vv, o);
            }
            if (t == 0) {
                out[0] = m / vv;
                g_count = 0;                    // reset for next graph replay
            }
        }
    }
}

extern "C" void kernel_launch(void* const* d_in, const int* in_sizes, int n_in,
                              void* d_out, int out_size) {
    const float* scores = (const float*)d_in[0];
    const int*   labels = (const int*)d_in[1];
    float* out = (float*)d_out;

    side_kernel<<<NBLK, NT>>>(scores, labels, out);
}

// round 14
// speedup vs baseline: 1.2712x; 1.2161x over previous
#include <cuda_runtime.h>
#include <cuda_bf16.h>

#define M 512
#define NBLK 1024          // 512 row-lines + 512 col-lines
#define MARGIN 0.2f
#define NT 256             // threads per CTA
#define NB 256             // buckets == threads

#define CNT_SHIFT 40
#define LOW_MASK  ((1ULL << CNT_SHIFT) - 1ULL)
#define FIX_SCALE 1048576.0f           // 2^20
#define FIX_INV   (1.0 / 1048576.0)
#define FIX_OFF   16.0f                // x in (-16,16) -> (x+16)*2^20 fits 25 bits

__device__ float2 g_partials[NBLK];
__device__ int    g_count = 0;     // last-block ticket; reset by the finalizing block

__global__ __launch_bounds__(NT, 8)
void side_kernel(const float* __restrict__ scores,
                 const int* __restrict__ labels,
                 float* __restrict__ out) {
    __shared__ unsigned long long hist[NB];  // [40,64)=count, [0,40)=fixed sum(x+16)
    __shared__ float NVS[M];                 // negs packed by bucket (exact floats)
    __shared__ int   off[NB];                // exclusive prefix of counts
    __shared__ float sufC[NB];               // # negs in buckets > t
    __shared__ float sufS[NB];               // sum of negs in buckets > t
    __shared__ unsigned long long wcp[8];
    __shared__ float warp_sums[8];
    __shared__ bool  is_last;

    const int b    = blockIdx.x;
    const int t    = threadIdx.x;
    const int lane = t & 31;
    const int w    = t >> 5;

    // each thread owns elements t and t+256 of the line
    int idx0, idx1;
    if (b < M) { idx0 = b * M + t;       idx1 = idx0 + NT; }
    else       { idx0 = t * M + (b - M); idx1 = idx0 + NT * M; }

    const float s0 = scores[idx0];
    const float s1 = scores[idx1];
    const bool  p0 = (labels[idx0] == 1);
    const bool  p1 = (labels[idx1] == 1);
    const float x0 = p0 ? s0 : (s0 + MARGIN);
    const float x1 = p1 ? s1 : (s1 + MARGIN);

    hist[t] = 0ULL;
    __syncthreads();

    // monotone bucket: floor((x+8)*16), clamped to [0,255].
    // floor+clamp monotone => cross-bucket suffix exact;
    // same-bucket pairs handled by direct relu on exact floats.
    const int k0 = max(0, min(NB - 1, __float2int_rd((x0 + 8.0f) * 16.0f)));
    const int k1 = max(0, min(NB - 1, __float2int_rd((x1 + 8.0f) * 16.0f)));

    // ---- histogram: ONE packed 64-bit atomic per neg; return gives rank ----
    int r0 = 0, r1 = 0;
    if (!p0) {
        unsigned v = (unsigned)((x0 + FIX_OFF) * FIX_SCALE);
        unsigned long long old = atomicAdd(&hist[k0], (1ULL << CNT_SHIFT) | (unsigned long long)v);
        r0 = (int)(old >> CNT_SHIFT);
    }
    if (!p1) {
        unsigned v = (unsigned)((x1 + FIX_OFF) * FIX_SCALE);
        unsigned long long old = atomicAdd(&hist[k1], (1ULL << CNT_SHIFT) | (unsigned long long)v);
        r1 = (int)(old >> CNT_SHIFT);
    }
    __syncthreads();

    // ---- block-wide inclusive scan over packed buckets ----
    const unsigned long long h0 = hist[t];
    unsigned long long hc = h0;
    #pragma unroll
    for (int o = 1; o < 32; o <<= 1) {
        unsigned long long n = __shfl_up_sync(0xffffffffu, hc, o);
        if (lane >= o) hc += n;
    }
    if (lane == 31) wcp[w] = hc;
    __syncthreads();

    if (t < 32) {
        unsigned long long ci = (t < 8) ? wcp[t] : 0ULL;
        #pragma unroll
        for (int o = 1; o < 8; o <<= 1) {
            unsigned long long n = __shfl_up_sync(0xffffffffu, ci, o);
            if (lane >= o) ci += n;
        }
        if (t < 8) wcp[t] = ci;          // inclusive warp totals
    }
    __syncthreads();

    const unsigned long long incP = hc + ((w > 0) ? wcp[w - 1] : 0ULL);
    const unsigned long long tot  = wcp[7];
    const int incC = (int)(incP >> CNT_SHIFT);
    const int c0i  = (int)(h0 >> CNT_SHIFT);
    const int nn   = (int)(tot >> CNT_SHIFT);

    // suffix = tot - inc: exact field-wise (suffix fields <= total fields)
    const unsigned long long sufP = tot - incP;
    const int  sCnt = (int)(sufP >> CNT_SHIFT);
    const unsigned long long sLow = sufP & LOW_MASK;

    off[t]  = incC - c0i;
    sufC[t] = (float)sCnt;
    sufS[t] = (float)((double)sLow * FIX_INV - (double)FIX_OFF * (double)sCnt);
    __syncthreads();

    // ---- scatter using ranks captured from the histogram atomic ----
    if (!p0) NVS[off[k0] + r0] = x0;
    if (!p1) NVS[off[k1] + r1] = x1;
    __syncthreads();

    // ---- per-pos evaluation: exact suffix part + same-bucket relu ----
    float total = 0.f;
    if (p0) {
        float a = fmaf(-sufC[k0], s0, sufS[k0]);
        const int j0 = off[k0];
        const int j1 = j0 + (int)(hist[k0] >> CNT_SHIFT);
        for (int j = j0; j < j1; j++)               // avg ~1 iteration
            a += fmaxf(NVS[j] - s0, 0.f);
        total += a;
    }
    if (p1) {
        float a = fmaf(-sufC[k1], s1, sufS[k1]);
        const int j0 = off[k1];
        const int j1 = j0 + (int)(hist[k1] >> CNT_SHIFT);
        for (int j = j0; j < j1; j++)
            a += fmaxf(NVS[j] - s1, 0.f);
        total += a;
    }

    // ---- deterministic CTA reduction ----
    #pragma unroll
    for (int o = 16; o > 0; o >>= 1)
        total += __shfl_down_sync(0xffffffffu, total, o);
    if (lane == 0) warp_sums[w] = total;
    __syncthreads();

    if (t < 32) {
        float v = (t < 8) ? warp_sums[t] : 0.f;
        #pragma unroll
        for (int o = 4; o > 0; o >>= 1)
            v += __shfl_down_sync(0xffffffffu, v, o);
        if (t == 0) {
            const int   np    = M - nn;
            const bool  valid = (np > 0) && (nn > 0);
            const float cntf  = (float)np * (float)nn;   // exact in fp32
            float2 p;
            p.x = valid ? (v / cntf) : 0.f;
            p.y = valid ? 1.f : 0.f;
            g_partials[b] = p;
            __threadfence();
            int cc2 = atomicAdd(&g_count, 1);
            is_last = (cc2 == NBLK - 1);
        }
    }
    __syncthreads();

    // ---- last block: fixed-order global reduction + finalize ----
    if (is_last) {
        float m = 0.f, vv = 0.f;
        #pragma unroll
        for (int i = t; i < NBLK; i += NT) {
            float2 p = g_partials[i];
            m  += p.x;
            vv += p.y;
        }
        #pragma unroll
        for (int o = 16; o > 0; o >>= 1) {
            m  += __shfl_down_sync(0xffffffffu, m, o);
            vv += __shfl_down_sync(0xffffffffu, vv, o);
        }
        if (lane == 0) { warp_sums[w] = m; sufC[w] = vv; }
        __syncthreads();
        if (t < 32) {
            m  = (t < 8) ? warp_sums[t] : 0.f;
            vv = (t < 8) ? sufC[t] : 0.f;
            #pragma unroll
            for (int o = 4; o > 0; o >>= 1) {
                m  += __shfl_down_sync(0xffffffffu, m, o);
                vv += __shfl_down_sync(0xffffffffu, vv, o);
            }
            if (t == 0) {
                out[0] = m / vv;
                g_count = 0;                    // reset for next graph replay
            }
        }
    }
}

extern "C" void kernel_launch(void* const* d_in, const int* in_sizes, int n_in,
                              void* d_out, int out_size) {
    const float* scores = (const float*)d_in[0];
    const int*   labels = (const int*)d_in[1];
    float* out = (float*)d_out;

    side_kernel<<<NBLK, NT>>>(scores, labels, out);
}